// round 9
// baseline (speedup 1.0000x reference)
#include <cuda_runtime.h>
#include <cuda.h>
#include <cuda_fp16.h>
#include <cstdint>

// ============================================================
// Problem sizes
// ============================================================
#define B_DIM 8192
#define K_DIM 4096
#define N_DIM 4096

// GEMM tiling
#define BM 128
#define BN 256
#define BK 128                 // per stage; stage = two 64-half sub-stages
#define NST 2
#define KITERS (K_DIM / BK)    // 32

#define A_HALF 16384           // 128 rows * 128B (64 halfs of k)
#define B_HALF 32768           // 256 rows * 128B
#define STAGE_BYTES (2 * (A_HALF + B_HALF))   // 98304

#define SM_ST0      1024                      // bias in [0,1024)
#define SMEM_BYTES  (SM_ST0 + NST * STAGE_BYTES)   // 197632

// ============================================================
// Device-global scratch
// ============================================================
__device__ __half g_Ah[(size_t)B_DIM * K_DIM];   // 64 MB  x as fp16
__device__ __half g_Bt[(size_t)N_DIM * K_DIM];   // 32 MB  sign(W)^T, K-major

// ============================================================
// Asm helpers
// ============================================================
__device__ __forceinline__ uint32_t smem_u32(const void* p) {
    uint32_t a;
    asm("{ .reg .u64 t; cvta.to.shared.u64 t, %1; cvt.u32.u64 %0, t; }" : "=r"(a) : "l"(p));
    return a;
}

__device__ __forceinline__ void cp_async16(uint32_t saddr, const void* gaddr) {
    asm volatile("cp.async.cg.shared.global [%0], [%1], 16;" :: "r"(saddr), "l"(gaddr));
}
#define CP_COMMIT() asm volatile("cp.async.commit_group;" ::: "memory")
template <int N>
__device__ __forceinline__ void cp_wait() {
    asm volatile("cp.async.wait_group %0;" :: "n"(N) : "memory");
}

#define LDSM_X4(d, addr) \
    asm volatile("ldmatrix.sync.aligned.m8n8.x4.shared.b16 {%0,%1,%2,%3}, [%4];" \
        : "=r"((d)[0]), "=r"((d)[1]), "=r"((d)[2]), "=r"((d)[3]) : "r"(addr))

__device__ __forceinline__ void mma16816(float* d,
                                         const uint32_t* a, uint32_t b0, uint32_t b1) {
    asm volatile(
        "mma.sync.aligned.m16n8k16.row.col.f32.f16.f16.f32 "
        "{%0,%1,%2,%3}, {%4,%5,%6,%7}, {%8,%9}, {%0,%1,%2,%3};"
        : "+f"(d[0]), "+f"(d[1]), "+f"(d[2]), "+f"(d[3])
        : "r"(a[0]), "r"(a[1]), "r"(a[2]), "r"(a[3]), "r"(b0), "r"(b1));
}

// ============================================================
// Fused prep: blocks [0,8192) convert x -> fp16 (block-chunked, MLP=4);
// blocks [8192,12288) build Bt[n][k] = sign(W[k][n]) (64x64 transpose)
// ============================================================
#define PREP_X_BLOCKS (B_DIM * K_DIM / 4 / 1024)   // 8192
#define PREP_BT_BLOCKS ((N_DIM / 64) * (K_DIM / 64)) // 4096

__global__ void __launch_bounds__(256)
prep_fused(const float4* __restrict__ x, uint2* __restrict__ xh,
           const float* __restrict__ w, __half* __restrict__ bt) {
    __shared__ float tile[64][65];
    const int tid = threadIdx.x;

    if (blockIdx.x < PREP_X_BLOCKS) {
        // ---- x fp32 -> fp16, coalesced, MLP=4 ----
        const int base = blockIdx.x * 1024 + tid;
        float4 v0 = x[base];
        float4 v1 = x[base + 256];
        float4 v2 = x[base + 512];
        float4 v3 = x[base + 768];
        uint2 o0, o1, o2, o3;
        {
            __half2 a = __floats2half2_rn(v0.x, v0.y), b = __floats2half2_rn(v0.z, v0.w);
            o0.x = *reinterpret_cast<uint32_t*>(&a); o0.y = *reinterpret_cast<uint32_t*>(&b);
        }
        {
            __half2 a = __floats2half2_rn(v1.x, v1.y), b = __floats2half2_rn(v1.z, v1.w);
            o1.x = *reinterpret_cast<uint32_t*>(&a); o1.y = *reinterpret_cast<uint32_t*>(&b);
        }
        {
            __half2 a = __floats2half2_rn(v2.x, v2.y), b = __floats2half2_rn(v2.z, v2.w);
            o2.x = *reinterpret_cast<uint32_t*>(&a); o2.y = *reinterpret_cast<uint32_t*>(&b);
        }
        {
            __half2 a = __floats2half2_rn(v3.x, v3.y), b = __floats2half2_rn(v3.z, v3.w);
            o3.x = *reinterpret_cast<uint32_t*>(&a); o3.y = *reinterpret_cast<uint32_t*>(&b);
        }
        xh[base]       = o0;
        xh[base + 256] = o1;
        xh[base + 512] = o2;
        xh[base + 768] = o3;
    } else {
        // ---- sign(W)^T 64x64 tile ----
        const int bid2 = blockIdx.x - PREP_X_BLOCKS;
        const int n_base = (bid2 & 63) * 64;
        const int k_base = (bid2 >> 6) * 64;
        const int tx = tid & 63;     // n
        const int ty = tid >> 6;     // 0..3

#pragma unroll
        for (int i = 0; i < 16; i++) {
            const int k = ty + 4 * i;
            tile[k][tx] = w[(size_t)(k_base + k) * N_DIM + n_base + tx];
        }
        __syncthreads();

        const int kq = tid & 15;     // k = 4*kq .. 4*kq+3
        const int nr = tid >> 4;     // 0..15
#pragma unroll
        for (int j = 0; j < 4; j++) {
            const int n = nr + 16 * j;
            float v0 = tile[4 * kq + 0][n];
            float v1 = tile[4 * kq + 1][n];
            float v2 = tile[4 * kq + 2][n];
            float v3 = tile[4 * kq + 3][n];
            auto sgn = [](float v) -> float { return (v > 0.f) ? 1.f : ((v < 0.f) ? -1.f : 0.f); };
            __half2 p0 = __floats2half2_rn(sgn(v0), sgn(v1));
            __half2 p1 = __floats2half2_rn(sgn(v2), sgn(v3));
            uint2 o;
            o.x = *reinterpret_cast<uint32_t*>(&p0);
            o.y = *reinterpret_cast<uint32_t*>(&p1);
            *reinterpret_cast<uint2*>(
                bt + (size_t)(n_base + n) * K_DIM + k_base + 4 * kq) = o;
        }
    }
}

// ============================================================
// Main GEMM: 256 threads = 8 warps (2x4), warp tile 64x64, BK=128,
// NST=2, ldmatrix.x4, register-double-buffered fragments.
// cp.async issuance spread across k-steps w=0..5 (4 chunks/step).
// ============================================================
__global__ void __launch_bounds__(256, 1)
binary_dense_gemm(const __half* __restrict__ Ah,
                  const __half* __restrict__ Bt,
                  const float* __restrict__ bias,
                  float* __restrict__ out) {
    extern __shared__ char smem_raw[];
    float* bias_sm = reinterpret_cast<float*>(smem_raw);
    const uint32_t sb = smem_u32(smem_raw);

    const int tid = threadIdx.x;
    const int wid = tid >> 5;
    const int lid = tid & 31;
    const int wm = wid >> 2;        // 0..1
    const int wn = wid & 3;         // 0..3

    // ---- tile rasterization: supergroups of 8 m-tiles x 16 n-tiles ----
    const int bid = blockIdx.x;
    const int gid = bid >> 7;
    const int rem = bid & 127;
    const int mt  = gid * 8 + (rem & 7);
    const int nt  = rem >> 3;
    const int m0  = mt * BM;
    const int n0  = nt * BN;

    bias_sm[tid] = bias[n0 + tid];

    // ---- cp.async mapping (per 64-half sub-stage): A 4 chunks, B 8 chunks ----
    uint32_t aOff[4]; int aGI[4];
#pragma unroll
    for (int i = 0; i < 4; i++) {
        int c = tid + i * 256, r = c >> 3, ch = c & 7;
        aOff[i] = r * 128 + ((ch ^ (r & 7)) << 4);
        aGI[i]  = r * K_DIM + ch * 8;
    }
    uint32_t bOff[8]; int bGI[8];
#pragma unroll
    for (int i = 0; i < 8; i++) {
        int c = tid + i * 256, r = c >> 3, ch = c & 7;
        bOff[i] = r * 128 + ((ch ^ (r & 7)) << 4);
        bGI[i]  = r * K_DIM + ch * 8;
    }

    const __half* gA = Ah + (size_t)m0 * K_DIM;
    const __half* gB = Bt + (size_t)n0 * K_DIM;

    // full-stage issue (prologue only)
    auto issue_stage = [&](int slot, int kt) {
        const uint32_t st = sb + SM_ST0 + slot * STAGE_BYTES;
        const int k0 = kt * BK;
#pragma unroll
        for (int h = 0; h < 2; h++)
#pragma unroll
            for (int i = 0; i < 4; i++)
                cp_async16(st + h * A_HALF + aOff[i], gA + aGI[i] + k0 + h * 64);
#pragma unroll
        for (int h = 0; h < 2; h++)
#pragma unroll
            for (int i = 0; i < 8; i++)
                cp_async16(st + 2 * A_HALF + h * B_HALF + bOff[i], gB + bGI[i] + k0 + h * 64);
    };

    // quarter issue: 4 of the 24 chunks (w in 0..5, constant after unroll)
    auto issue_quarter = [&](int w, int slot, int ktn) {
        const uint32_t st = sb + SM_ST0 + slot * STAGE_BYTES;
        const int k0 = ktn * BK;
#pragma unroll
        for (int q = 0; q < 4; q++) {
            const int c = w * 4 + q;
            if (c < 8) {
                const int h = c >> 2, i = c & 3;
                cp_async16(st + h * A_HALF + aOff[i], gA + aGI[i] + k0 + h * 64);
            } else {
                const int cb = c - 8, h = cb >> 3, i = cb & 7;
                cp_async16(st + 2 * A_HALF + h * B_HALF + bOff[i], gB + bGI[i] + k0 + h * 64);
            }
        }
    };

    // ---- ldmatrix lane addressing ----
    const int hbA = lid >> 4;
    uint32_t aRowByte[4], aR7[4];
#pragma unroll
    for (int i = 0; i < 4; i++) {
        int r = wm * 64 + i * 16 + (lid & 15);
        aRowByte[i] = r * 128;
        aR7[i] = r & 7;
    }
    const int hbB = (lid >> 3) & 1;
    uint32_t bRowByte[4], bR7[4];
#pragma unroll
    for (int j = 0; j < 4; j++) {
        int r = wn * 64 + j * 16 + ((lid >> 4) << 3) + (lid & 7);
        bRowByte[j] = r * 128;
        bR7[j] = r & 7;
    }

    float acc[4][8][4];
#pragma unroll
    for (int i = 0; i < 4; i++)
#pragma unroll
        for (int j = 0; j < 8; j++)
#pragma unroll
            for (int q = 0; q < 4; q++) acc[i][j][q] = 0.f;

    uint32_t af[2][4][4], bf[2][4][4];

    // ---- prologue: stage 0, then first fragments ----
    issue_stage(0, 0); CP_COMMIT();
    cp_wait<0>();
    __syncthreads();
    {
        const uint32_t stA = sb + SM_ST0;
        const uint32_t stB = stA + 2 * A_HALF;
#pragma unroll
        for (int i = 0; i < 4; i++)
            LDSM_X4(af[0][i], stA + aRowByte[i] + ((uint32_t)(hbA ^ aR7[i]) << 4));
#pragma unroll
        for (int j = 0; j < 4; j++)
            LDSM_X4(bf[0][j], stB + bRowByte[j] + ((uint32_t)(hbB ^ bR7[j]) << 4));
    }

    for (int kt = 0; kt < KITERS; kt++) {
        const bool more = (kt + 1 < KITERS);
        const int nslot = (kt + 1) & 1;

        const uint32_t stA = sb + SM_ST0 + (kt & 1) * STAGE_BYTES;
        const uint32_t stB = stA + 2 * A_HALF;
        const uint32_t nstA = sb + SM_ST0 + nslot * STAGE_BYTES;
        const uint32_t nstB = nstA + 2 * A_HALF;

#pragma unroll
        for (int w = 0; w < 8; w++) {          // eight k16 steps per BK=128
            const int cur = w & 1, nxt = cur ^ 1;

            // spread next-stage loads across w=0..5
            if (w < 6 && more) issue_quarter(w, nslot, kt + 1);
            if (w == 5) CP_COMMIT();

            if (w < 7) {
                const int h2  = (w + 1) >> 2;
                const int wk2 = (w + 1) & 3;
                const uint32_t bA = stA + h2 * A_HALF;
                const uint32_t bB = stB + h2 * B_HALF;
#pragma unroll
                for (int i = 0; i < 4; i++)
                    LDSM_X4(af[nxt][i],
                            bA + aRowByte[i] + ((uint32_t)((2 * wk2 + hbA) ^ aR7[i]) << 4));
#pragma unroll
                for (int j = 0; j < 4; j++)
                    LDSM_X4(bf[nxt][j],
                            bB + bRowByte[j] + ((uint32_t)((2 * wk2 + hbB) ^ bR7[j]) << 4));
            } else {
                cp_wait<0>();
                __syncthreads();
                if (more) {
#pragma unroll
                    for (int i = 0; i < 4; i++)
                        LDSM_X4(af[nxt][i],
                                nstA + aRowByte[i] + ((uint32_t)(hbA ^ aR7[i]) << 4));
#pragma unroll
                    for (int j = 0; j < 4; j++)
                        LDSM_X4(bf[nxt][j],
                                nstB + bRowByte[j] + ((uint32_t)(hbB ^ bR7[j]) << 4));
                }
            }

#pragma unroll
            for (int i = 0; i < 4; i++)
#pragma unroll
                for (int j = 0; j < 4; j++) {
                    mma16816(acc[i][2 * j],     af[cur][i], bf[cur][j][0], bf[cur][j][1]);
                    mma16816(acc[i][2 * j + 1], af[cur][i], bf[cur][j][2], bf[cur][j][3]);
                }
        }
    }

    // ---- epilogue ----
    const int r4 = lid >> 2, c4 = lid & 3;
#pragma unroll
    for (int i = 0; i < 4; i++) {
        const int row = m0 + wm * 64 + i * 16 + r4;
        float* o0 = out + (size_t)row * N_DIM + n0;
        float* o1 = out + (size_t)(row + 8) * N_DIM + n0;
#pragma unroll
        for (int j = 0; j < 8; j++) {
            const int col = wn * 64 + j * 8 + c4 * 2;
            const float b0 = bias_sm[col], b1 = bias_sm[col + 1];
            float2 v0 = make_float2(acc[i][j][0] + b0, acc[i][j][1] + b1);
            float2 v1 = make_float2(acc[i][j][2] + b0, acc[i][j][3] + b1);
            *reinterpret_cast<float2*>(o0 + col) = v0;
            *reinterpret_cast<float2*>(o1 + col) = v1;
        }
    }
}

// ============================================================
// Host side
// ============================================================
extern "C" void kernel_launch(void* const* d_in, const int* in_sizes, int n_in,
                              void* d_out, int out_size) {
    const float* x    = (const float*)d_in[0];
    const float* w    = (const float*)d_in[1];
    const float* bias = (const float*)d_in[2];
    float* out        = (float*)d_out;

    void *p_ah = nullptr, *p_bt = nullptr;
    cudaGetSymbolAddress(&p_ah, g_Ah);
    cudaGetSymbolAddress(&p_bt, g_Bt);

    prep_fused<<<PREP_X_BLOCKS + PREP_BT_BLOCKS, 256>>>(
        (const float4*)x, (uint2*)p_ah, w, (__half*)p_bt);

    static bool attr_set = false;
    if (!attr_set) {
        cudaFuncSetAttribute(binary_dense_gemm,
                             cudaFuncAttributeMaxDynamicSharedMemorySize, SMEM_BYTES);
        attr_set = true;
    }
    const int grid = (B_DIM / BM) * (N_DIM / BN);   // 1024
    binary_dense_gemm<<<grid, 256, SMEM_BYTES>>>(
        (const __half*)p_ah, (const __half*)p_bt, bias, out);
}

// round 10
// speedup vs baseline: 1.0470x; 1.0470x over previous
#include <cuda_runtime.h>
#include <cuda.h>
#include <cuda_fp16.h>
#include <cstdint>

// ============================================================
// Problem sizes
// ============================================================
#define B_DIM 8192
#define K_DIM 4096
#define N_DIM 4096

// GEMM tiling
#define BM 128
#define BN 256
#define BK 128                 // per stage; stage = two 64-half sub-stages
#define NST 2
#define KITERS (K_DIM / BK)    // 32

#define A_HALF 16384           // 128 rows * 128B (64 halfs of k)
#define B_HALF 32768           // 256 rows * 128B
#define STAGE_BYTES (2 * (A_HALF + B_HALF))   // 98304

#define SM_ST0      1024                      // bias in [0,1024)
#define SMEM_BYTES  (SM_ST0 + NST * STAGE_BYTES)   // 197632

// ============================================================
// Device-global scratch
// ============================================================
__device__ __half g_Ah[(size_t)B_DIM * K_DIM];   // 64 MB  x as fp16
__device__ __half g_Bt[(size_t)N_DIM * K_DIM];   // 32 MB  sign(W)^T, K-major

// ============================================================
// Asm helpers
// ============================================================
__device__ __forceinline__ uint32_t smem_u32(const void* p) {
    uint32_t a;
    asm("{ .reg .u64 t; cvta.to.shared.u64 t, %1; cvt.u32.u64 %0, t; }" : "=r"(a) : "l"(p));
    return a;
}

__device__ __forceinline__ void cp_async16(uint32_t saddr, const void* gaddr) {
    asm volatile("cp.async.cg.shared.global [%0], [%1], 16;" :: "r"(saddr), "l"(gaddr));
}
#define CP_COMMIT() asm volatile("cp.async.commit_group;" ::: "memory")
template <int N>
__device__ __forceinline__ void cp_wait() {
    asm volatile("cp.async.wait_group %0;" :: "n"(N) : "memory");
}

#define LDSM_X4(d, addr) \
    asm volatile("ldmatrix.sync.aligned.m8n8.x4.shared.b16 {%0,%1,%2,%3}, [%4];" \
        : "=r"((d)[0]), "=r"((d)[1]), "=r"((d)[2]), "=r"((d)[3]) : "r"(addr))

__device__ __forceinline__ void mma16816(float* d,
                                         const uint32_t* a, uint32_t b0, uint32_t b1) {
    asm volatile(
        "mma.sync.aligned.m16n8k16.row.col.f32.f16.f16.f32 "
        "{%0,%1,%2,%3}, {%4,%5,%6,%7}, {%8,%9}, {%0,%1,%2,%3};"
        : "+f"(d[0]), "+f"(d[1]), "+f"(d[2]), "+f"(d[3])
        : "r"(a[0]), "r"(a[1]), "r"(a[2]), "r"(a[3]), "r"(b0), "r"(b1));
}

// ============================================================
// Fused prep (validated in R9): blocks [0,8192) convert x -> fp16
// (block-chunked, MLP=4); blocks [8192,12288) build
// Bt[n][k] = sign(W[k][n]) (64x64 transpose, coalesced uint2 writes)
// ============================================================
#define PREP_X_BLOCKS (B_DIM * K_DIM / 4 / 1024)     // 8192
#define PREP_BT_BLOCKS ((N_DIM / 64) * (K_DIM / 64)) // 4096

__global__ void __launch_bounds__(256)
prep_fused(const float4* __restrict__ x, uint2* __restrict__ xh,
           const float* __restrict__ w, __half* __restrict__ bt) {
    __shared__ float tile[64][65];
    const int tid = threadIdx.x;

    if (blockIdx.x < PREP_X_BLOCKS) {
        const int base = blockIdx.x * 1024 + tid;
        float4 v0 = x[base];
        float4 v1 = x[base + 256];
        float4 v2 = x[base + 512];
        float4 v3 = x[base + 768];
        uint2 o0, o1, o2, o3;
        {
            __half2 a = __floats2half2_rn(v0.x, v0.y), b = __floats2half2_rn(v0.z, v0.w);
            o0.x = *reinterpret_cast<uint32_t*>(&a); o0.y = *reinterpret_cast<uint32_t*>(&b);
        }
        {
            __half2 a = __floats2half2_rn(v1.x, v1.y), b = __floats2half2_rn(v1.z, v1.w);
            o1.x = *reinterpret_cast<uint32_t*>(&a); o1.y = *reinterpret_cast<uint32_t*>(&b);
        }
        {
            __half2 a = __floats2half2_rn(v2.x, v2.y), b = __floats2half2_rn(v2.z, v2.w);
            o2.x = *reinterpret_cast<uint32_t*>(&a); o2.y = *reinterpret_cast<uint32_t*>(&b);
        }
        {
            __half2 a = __floats2half2_rn(v3.x, v3.y), b = __floats2half2_rn(v3.z, v3.w);
            o3.x = *reinterpret_cast<uint32_t*>(&a); o3.y = *reinterpret_cast<uint32_t*>(&b);
        }
        xh[base]       = o0;
        xh[base + 256] = o1;
        xh[base + 512] = o2;
        xh[base + 768] = o3;
    } else {
        const int bid2 = blockIdx.x - PREP_X_BLOCKS;
        const int n_base = (bid2 & 63) * 64;
        const int k_base = (bid2 >> 6) * 64;
        const int tx = tid & 63;     // n
        const int ty = tid >> 6;     // 0..3

#pragma unroll
        for (int i = 0; i < 16; i++) {
            const int k = ty + 4 * i;
            tile[k][tx] = w[(size_t)(k_base + k) * N_DIM + n_base + tx];
        }
        __syncthreads();

        const int kq = tid & 15;     // k = 4*kq .. 4*kq+3
        const int nr = tid >> 4;     // 0..15
#pragma unroll
        for (int j = 0; j < 4; j++) {
            const int n = nr + 16 * j;
            float v0 = tile[4 * kq + 0][n];
            float v1 = tile[4 * kq + 1][n];
            float v2 = tile[4 * kq + 2][n];
            float v3 = tile[4 * kq + 3][n];
            auto sgn = [](float v) -> float { return (v > 0.f) ? 1.f : ((v < 0.f) ? -1.f : 0.f); };
            __half2 p0 = __floats2half2_rn(sgn(v0), sgn(v1));
            __half2 p1 = __floats2half2_rn(sgn(v2), sgn(v3));
            uint2 o;
            o.x = *reinterpret_cast<uint32_t*>(&p0);
            o.y = *reinterpret_cast<uint32_t*>(&p1);
            *reinterpret_cast<uint2*>(
                bt + (size_t)(n_base + n) * K_DIM + k_base + 4 * kq) = o;
        }
    }
}

// ============================================================
// Main GEMM — exact R8 version (best measured GEMM: ~520us, tensor ~87%):
// 256 threads = 8 warps (2x4), warp tile 64x64, BK=128, NST=2,
// ldmatrix.x4, register-double-buffered fragments,
// full-stage cp.async burst at top of iteration.
// ============================================================
__global__ void __launch_bounds__(256, 1)
binary_dense_gemm(const __half* __restrict__ Ah,
                  const __half* __restrict__ Bt,
                  const float* __restrict__ bias,
                  float* __restrict__ out) {
    extern __shared__ char smem_raw[];
    float* bias_sm = reinterpret_cast<float*>(smem_raw);
    const uint32_t sb = smem_u32(smem_raw);

    const int tid = threadIdx.x;
    const int wid = tid >> 5;
    const int lid = tid & 31;
    const int wm = wid >> 2;        // 0..1
    const int wn = wid & 3;         // 0..3

    // ---- tile rasterization: supergroups of 8 m-tiles x 16 n-tiles ----
    const int bid = blockIdx.x;
    const int gid = bid >> 7;
    const int rem = bid & 127;
    const int mt  = gid * 8 + (rem & 7);
    const int nt  = rem >> 3;
    const int m0  = mt * BM;
    const int n0  = nt * BN;

    bias_sm[tid] = bias[n0 + tid];

    // ---- cp.async mapping (per 64-half sub-stage): A 4 chunks, B 8 chunks ----
    uint32_t aOff[4]; int aGI[4];
#pragma unroll
    for (int i = 0; i < 4; i++) {
        int c = tid + i * 256, r = c >> 3, ch = c & 7;
        aOff[i] = r * 128 + ((ch ^ (r & 7)) << 4);
        aGI[i]  = r * K_DIM + ch * 8;
    }
    uint32_t bOff[8]; int bGI[8];
#pragma unroll
    for (int i = 0; i < 8; i++) {
        int c = tid + i * 256, r = c >> 3, ch = c & 7;
        bOff[i] = r * 128 + ((ch ^ (r & 7)) << 4);
        bGI[i]  = r * K_DIM + ch * 8;
    }

    const __half* gA = Ah + (size_t)m0 * K_DIM;
    const __half* gB = Bt + (size_t)n0 * K_DIM;

    auto issue_stage = [&](int slot, int kt) {
        const uint32_t st = sb + SM_ST0 + slot * STAGE_BYTES;
        const int k0 = kt * BK;
#pragma unroll
        for (int h = 0; h < 2; h++)
#pragma unroll
            for (int i = 0; i < 4; i++)
                cp_async16(st + h * A_HALF + aOff[i], gA + aGI[i] + k0 + h * 64);
#pragma unroll
        for (int h = 0; h < 2; h++)
#pragma unroll
            for (int i = 0; i < 8; i++)
                cp_async16(st + 2 * A_HALF + h * B_HALF + bOff[i], gB + bGI[i] + k0 + h * 64);
    };

    // ---- ldmatrix lane addressing ----
    const int hbA = lid >> 4;
    uint32_t aRowByte[4], aR7[4];
#pragma unroll
    for (int i = 0; i < 4; i++) {
        int r = wm * 64 + i * 16 + (lid & 15);
        aRowByte[i] = r * 128;
        aR7[i] = r & 7;
    }
    const int hbB = (lid >> 3) & 1;
    uint32_t bRowByte[4], bR7[4];
#pragma unroll
    for (int j = 0; j < 4; j++) {
        int r = wn * 64 + j * 16 + ((lid >> 4) << 3) + (lid & 7);
        bRowByte[j] = r * 128;
        bR7[j] = r & 7;
    }

    float acc[4][8][4];
#pragma unroll
    for (int i = 0; i < 4; i++)
#pragma unroll
        for (int j = 0; j < 8; j++)
#pragma unroll
            for (int q = 0; q < 4; q++) acc[i][j][q] = 0.f;

    uint32_t af[2][4][4], bf[2][4][4];

    // ---- prologue: stage 0, then first fragments ----
    issue_stage(0, 0); CP_COMMIT();
    cp_wait<0>();
    __syncthreads();
    {
        const uint32_t stA = sb + SM_ST0;
        const uint32_t stB = stA + 2 * A_HALF;
#pragma unroll
        for (int i = 0; i < 4; i++)
            LDSM_X4(af[0][i], stA + aRowByte[i] + ((uint32_t)(hbA ^ aR7[i]) << 4));
#pragma unroll
        for (int j = 0; j < 4; j++)
            LDSM_X4(bf[0][j], stB + bRowByte[j] + ((uint32_t)(hbB ^ bR7[j]) << 4));
    }

    for (int kt = 0; kt < KITERS; kt++) {
        if (kt + 1 < KITERS) issue_stage((kt + 1) & 1, kt + 1);
        CP_COMMIT();

        const uint32_t stA = sb + SM_ST0 + (kt & 1) * STAGE_BYTES;
        const uint32_t stB = stA + 2 * A_HALF;
        const uint32_t nstA = sb + SM_ST0 + ((kt + 1) & 1) * STAGE_BYTES;
        const uint32_t nstB = nstA + 2 * A_HALF;

#pragma unroll
        for (int w = 0; w < 8; w++) {          // eight k16 steps per BK=128
            const int cur = w & 1, nxt = cur ^ 1;

            if (w < 7) {
                const int h2  = (w + 1) >> 2;
                const int wk2 = (w + 1) & 3;
                const uint32_t bA = stA + h2 * A_HALF;
                const uint32_t bB = stB + h2 * B_HALF;
#pragma unroll
                for (int i = 0; i < 4; i++)
                    LDSM_X4(af[nxt][i],
                            bA + aRowByte[i] + ((uint32_t)((2 * wk2 + hbA) ^ aR7[i]) << 4));
#pragma unroll
                for (int j = 0; j < 4; j++)
                    LDSM_X4(bf[nxt][j],
                            bB + bRowByte[j] + ((uint32_t)((2 * wk2 + hbB) ^ bR7[j]) << 4));
            } else {
                cp_wait<0>();
                __syncthreads();
                if (kt + 1 < KITERS) {
#pragma unroll
                    for (int i = 0; i < 4; i++)
                        LDSM_X4(af[nxt][i],
                                nstA + aRowByte[i] + ((uint32_t)(hbA ^ aR7[i]) << 4));
#pragma unroll
                    for (int j = 0; j < 4; j++)
                        LDSM_X4(bf[nxt][j],
                                nstB + bRowByte[j] + ((uint32_t)(hbB ^ bR7[j]) << 4));
                }
            }

#pragma unroll
            for (int i = 0; i < 4; i++)
#pragma unroll
                for (int j = 0; j < 4; j++) {
                    mma16816(acc[i][2 * j],     af[cur][i], bf[cur][j][0], bf[cur][j][1]);
                    mma16816(acc[i][2 * j + 1], af[cur][i], bf[cur][j][2], bf[cur][j][3]);
                }
        }
    }

    // ---- epilogue ----
    const int r4 = lid >> 2, c4 = lid & 3;
#pragma unroll
    for (int i = 0; i < 4; i++) {
        const int row = m0 + wm * 64 + i * 16 + r4;
        float* o0 = out + (size_t)row * N_DIM + n0;
        float* o1 = out + (size_t)(row + 8) * N_DIM + n0;
#pragma unroll
        for (int j = 0; j < 8; j++) {
            const int col = wn * 64 + j * 8 + c4 * 2;
            const float b0 = bias_sm[col], b1 = bias_sm[col + 1];
            float2 v0 = make_float2(acc[i][j][0] + b0, acc[i][j][1] + b1);
            float2 v1 = make_float2(acc[i][j][2] + b0, acc[i][j][3] + b1);
            *reinterpret_cast<float2*>(o0 + col) = v0;
            *reinterpret_cast<float2*>(o1 + col) = v1;
        }
    }
}

// ============================================================
// Host side
// ============================================================
extern "C" void kernel_launch(void* const* d_in, const int* in_sizes, int n_in,
                              void* d_out, int out_size) {
    const float* x    = (const float*)d_in[0];
    const float* w    = (const float*)d_in[1];
    const float* bias = (const float*)d_in[2];
    float* out        = (float*)d_out;

    void *p_ah = nullptr, *p_bt = nullptr;
    cudaGetSymbolAddress(&p_ah, g_Ah);
    cudaGetSymbolAddress(&p_bt, g_Bt);

    prep_fused<<<PREP_X_BLOCKS + PREP_BT_BLOCKS, 256>>>(
        (const float4*)x, (uint2*)p_ah, w, (__half*)p_bt);

    static bool attr_set = false;
    if (!attr_set) {
        cudaFuncSetAttribute(binary_dense_gemm,
                             cudaFuncAttributeMaxDynamicSharedMemorySize, SMEM_BYTES);
        attr_set = true;
    }
    const int grid = (B_DIM / BM) * (N_DIM / BN);   // 1024
    binary_dense_gemm<<<grid, 256, SMEM_BYTES>>>(
        (const __half*)p_ah, (const __half*)p_bt, bias, out);
}